// round 13
// baseline (speedup 1.0000x reference)
#include <cuda_runtime.h>
#include <math.h>

#define BB 64
#define WW 4096
#define HH 128
#define WC 128
#define CHUNKS 32    // WW / WC
#define NT1 256      // attn threads

// ---------------- scratch (__device__ globals, allocation-free) -------------
// NOTE: never pass these as kernel arguments from host code — host sees a
// shadow symbol and ATS makes the GPU silently read host memory (zeros).
__device__ float g_m[BB * CHUNKS];
__device__ float g_s[BB * CHUNKS];
__device__ float g_acc[BB * CHUNKS * HH];
__device__ float g_xT[2 * HH * BB];      // xcat transposed [k][b]: k<128 ctx, k>=128 input
__device__ float g_h0l0T[HH * BB];       // h0 layer0 transposed [h][b]
__device__ float g_h0l1T[HH * BB];       // h0 layer1 transposed
__device__ float g_h1T[HH * BB];         // h1 (LSTM0 out) transposed
__device__ float g_xinT[HH * BB];        // xin transposed [r][b] (bias included)
__device__ float g_gatesT[4 * HH * BB];  // gates transposed [g][b] (biases included)

// ---------------------------------------------------------------------------
// Kernel 1: per-(batch, chunk=128) partial attention with softmax partials.
// 256 threads, ~65KB smem -> 3 CTAs/SM so load/compute phases overlap
// across co-resident CTAs.
// ---------------------------------------------------------------------------
__global__ __launch_bounds__(NT1) void attn_partial(
    const float* __restrict__ enc,   // (B, W, H)
    const float* __restrict__ h0,    // (2, B, H)
    const float* __restrict__ c0,    // (2, B, H)
    const float* __restrict__ attW,  // (1, 2H)
    const float* __restrict__ attb)  // (1,)
{
    extern __shared__ float sm[];
    float* enc_s = sm;                   // (WC+1)*HH floats (row j = global row r0-1+j)
    float* sc    = sm + (WC + 1) * HH;   // 132 scores / probs
    float* red   = sc + 132;             // 8-entry reduce scratch

    const int b = blockIdx.y, c = blockIdx.x;
    const int t = threadIdx.x, lane = t & 31, wrp = t >> 5;
    const int r0 = c * WC;

    // ---- scalar bias: att_state[b].wa_st + att_b ----
    float tb = 0.f;
    if (t < HH) {
        float hv = h0[(BB + b) * HH + t];
        float cv = c0[(BB + b) * HH + t];
        tb = hv * cv * attW[HH + t];
    }
    #pragma unroll
    for (int o = 16; o > 0; o >>= 1) tb += __shfl_xor_sync(0xffffffffu, tb, o);
    if (lane == 0) red[wrp] = tb;

    // ---- bulk coalesced copy: 129 rows * 32 float4 ----
    {
        const float4* encv = reinterpret_cast<const float4*>(enc) + (long)b * WW * 32;
        float4* dst = reinterpret_cast<float4*>(enc_s);
        const int base = (r0 - 1) * 32;
        for (int q = t; q < (WC + 1) * 32; q += NT1) {
            const int gq = base + q;
            float4 v = make_float4(0.f, 0.f, 0.f, 0.f);
            if (gq >= 0) v = encv[gq];
            dst[q] = v;
        }
    }
    __syncthreads();

    float tbias = attb[0];
    #pragma unroll
    for (int g = 0; g < 8; ++g) tbias += red[g];

    // ---- scores from SMEM, warp-per-row ----
    const float4 wa = reinterpret_cast<const float4*>(attW)[lane];
    const float4* es = reinterpret_cast<const float4*>(enc_s);
    for (int j = wrp; j < WC; j += 8) {
        float4 e = es[j * 32 + lane];
        float d = e.x * wa.x + e.y * wa.y + e.z * wa.z + e.w * wa.w;
        #pragma unroll
        for (int o = 16; o > 0; o >>= 1) d += __shfl_xor_sync(0xffffffffu, d, o);
        if (lane == 0) sc[j] = d + tbias;
    }
    __syncthreads();

    // ---- local softmax: weight w = r0+t uses score(w-1)=sc[t]; w==0 -> 0 ----
    float l = -INFINITY;
    if (t < WC) {
        l = sc[t];
        if (r0 + t == 0) l = 0.f;
    }
    float m = l;
    #pragma unroll
    for (int o = 16; o > 0; o >>= 1) m = fmaxf(m, __shfl_xor_sync(0xffffffffu, m, o));
    if (lane == 0) red[wrp] = m;
    __syncthreads();
    float M = red[0];
    #pragma unroll
    for (int g = 1; g < 8; ++g) M = fmaxf(M, red[g]);
    __syncthreads();

    float p = (t < WC) ? __expf(l - M) : 0.f;
    if (t < WC) sc[t] = p;
    float s = p;
    #pragma unroll
    for (int o = 16; o > 0; o >>= 1) s += __shfl_xor_sync(0xffffffffu, s, o);
    if (lane == 0) red[wrp] = s;
    __syncthreads();
    float S = 0.f;
    #pragma unroll
    for (int g = 0; g < 8; ++g) S += red[g];

    // ---- weighted sum: 16 rows per warp, lane = float4 column ----
    float4 acc = make_float4(0.f, 0.f, 0.f, 0.f);
    #pragma unroll
    for (int i = wrp * 16; i < wrp * 16 + 16; ++i) {
        float pv = sc[i];
        float4 e = es[(i + 1) * 32 + lane];
        acc.x += pv * e.x; acc.y += pv * e.y; acc.z += pv * e.z; acc.w += pv * e.w;
    }
    __syncthreads();
    float4* rbuf = reinterpret_cast<float4*>(enc_s);
    rbuf[wrp * 32 + lane] = acc;
    __syncthreads();
    if (wrp == 0) {
        float4 a = rbuf[lane];
        #pragma unroll
        for (int g = 1; g < 8; ++g) {
            float4 e = rbuf[g * 32 + lane];
            a.x += e.x; a.y += e.y; a.z += e.z; a.w += e.w;
        }
        reinterpret_cast<float4*>(g_acc + (b * CHUNKS + c) * HH)[lane] = a;
    }
    if (t == 0) { g_m[b * CHUNKS + c] = M; g_s[b * CHUNKS + c] = S; }
}

// ---------------------------------------------------------------------------
// K2a: combine chunk partials -> context x; stage transposed activations.
// ---------------------------------------------------------------------------
__global__ __launch_bounds__(128) void combine_stage(
    const float* __restrict__ input, const float* __restrict__ h0)
{
    const int b = blockIdx.x, t = threadIdx.x;   // t < 128
    float M = -INFINITY;
    #pragma unroll
    for (int c = 0; c < CHUNKS; ++c) M = fmaxf(M, g_m[b * CHUNKS + c]);
    float S = 0.f, a = 0.f;
    #pragma unroll
    for (int c = 0; c < CHUNKS; ++c) {
        float e = __expf(g_m[b * CHUNKS + c] - M);
        S += g_s[b * CHUNKS + c] * e;
        a += g_acc[(b * CHUNKS + c) * HH + t] * e;
    }
    g_xT[t * BB + b] = a / S;
    g_xT[(HH + t) * BB + b] = input[b * HH + t];
    g_h0l0T[t * BB + b] = h0[b * HH + t];
    g_h0l1T[t * BB + b] = h0[BB * HH + b * HH + t];
}

// ---------------------------------------------------------------------------
// K2b: xin[r][b] = inpb[r] + sum_k inpW[r][k] * xcat[k][b].
// Batch-in-lane GEMV: warp w -> row r, lane -> batches {lane, lane+32}.
// xcat staged in SMEM [k][b]. grid = 16 CTAs x 256 threads (128 rows).
// ---------------------------------------------------------------------------
__global__ __launch_bounds__(256) void xin_gemv(
    const float* __restrict__ inpW, const float* __restrict__ inpb)
{
    extern __shared__ float xs[];                  // 2*HH*BB = 64KB
    const int t = threadIdx.x, lane = t & 31, wrp = t >> 5;
    for (int i = t; i < 2 * HH * BB; i += 256) xs[i] = g_xT[i];
    __syncthreads();

    const int r = blockIdx.x * 8 + wrp;            // 0..127
    const float4* w4 = reinterpret_cast<const float4*>(inpW + r * (2 * HH));
    float a0 = 0.f, a1 = 0.f;
    #pragma unroll 8
    for (int kk = 0; kk < 64; ++kk) {              // 64 float4 = 256 k
        float4 wv = w4[kk];
        const float* x0 = xs + (kk * 4) * BB + lane;
        a0 += wv.x * x0[0]  + wv.y * x0[BB]      + wv.z * x0[2 * BB]      + wv.w * x0[3 * BB];
        a1 += wv.x * x0[32] + wv.y * x0[BB + 32] + wv.z * x0[2 * BB + 32] + wv.w * x0[3 * BB + 32];
    }
    float bv = inpb[r];
    g_xinT[r * BB + lane]      = a0 + bv;
    g_xinT[r * BB + 32 + lane] = a1 + bv;
}

// ---------------------------------------------------------------------------
// K2c: gates[g][b] = bih[g]+bhh[g] + sum_k Wih[g][k]*x[k][b] + Whh[g][k]*h[k][b]
// grid = 64 CTAs x 256 threads (512 gate rows). x/h picked from g_* scratch
// IN DEVICE CODE via the layer flag (never passed as host args).
// ---------------------------------------------------------------------------
__global__ __launch_bounds__(256) void gates_gemv(
    const float* __restrict__ Wih, const float* __restrict__ Whh,
    const float* __restrict__ bih, const float* __restrict__ bhh,
    int layer)
{
    extern __shared__ float sh[];                  // 2*HH*BB = 64KB
    float* xsh = sh;                               // [k][b], k<128
    float* hsh = sh + HH * BB;
    const float* xT = layer ? g_h1T   : g_xinT;    // device-side symbol refs
    const float* hT = layer ? g_h0l1T : g_h0l0T;
    const int t = threadIdx.x, lane = t & 31, wrp = t >> 5;
    for (int i = t; i < HH * BB; i += 256) { xsh[i] = xT[i]; hsh[i] = hT[i]; }
    __syncthreads();

    const int r = blockIdx.x * 8 + wrp;            // 0..511
    const float4* wi4 = reinterpret_cast<const float4*>(Wih + r * HH);
    const float4* wh4 = reinterpret_cast<const float4*>(Whh + r * HH);
    float a0 = 0.f, a1 = 0.f;
    #pragma unroll 8
    for (int kk = 0; kk < 32; ++kk) {              // 32 float4 = 128 k
        float4 wv = wi4[kk];
        const float* x0 = xsh + (kk * 4) * BB + lane;
        a0 += wv.x * x0[0]  + wv.y * x0[BB]      + wv.z * x0[2 * BB]      + wv.w * x0[3 * BB];
        a1 += wv.x * x0[32] + wv.y * x0[BB + 32] + wv.z * x0[2 * BB + 32] + wv.w * x0[3 * BB + 32];
    }
    #pragma unroll 8
    for (int kk = 0; kk < 32; ++kk) {
        float4 wv = wh4[kk];
        const float* h0p = hsh + (kk * 4) * BB + lane;
        a0 += wv.x * h0p[0]  + wv.y * h0p[BB]      + wv.z * h0p[2 * BB]      + wv.w * h0p[3 * BB];
        a1 += wv.x * h0p[32] + wv.y * h0p[BB + 32] + wv.z * h0p[2 * BB + 32] + wv.w * h0p[3 * BB + 32];
    }
    float bv = bih[r] + bhh[r];
    g_gatesT[r * BB + lane]      = a0 + bv;
    g_gatesT[r * BB + 32 + lane] = a1 + bv;
}

// ---------------------------------------------------------------------------
// K2d: LSTM elementwise (biases already in g_gatesT).
// ---------------------------------------------------------------------------
__device__ __forceinline__ float sigmoidf_(float v) { return 1.0f / (1.0f + __expf(-v)); }

__global__ __launch_bounds__(512) void lstm_elem(
    const float* __restrict__ c0,      // base pointer (real device ptr)
    float* __restrict__ out, int layer)
{
    const float* c0ptr = c0 + layer * BB * HH;
    const int idx = blockIdx.x * 512 + threadIdx.x;  // 0..8191
    const int b = idx & 63, h = idx >> 6;
    float G0 = g_gatesT[(0 * HH + h) * BB + b];
    float G1 = g_gatesT[(1 * HH + h) * BB + b];
    float G2 = g_gatesT[(2 * HH + h) * BB + b];
    float G3 = g_gatesT[(3 * HH + h) * BB + b];
    float ig = sigmoidf_(G0);
    float fg = sigmoidf_(G1);
    float gg = tanhf(G2);
    float og = sigmoidf_(G3);
    float cn = fg * c0ptr[b * HH + h] + ig * gg;
    float hn = og * tanhf(cn);
    if (layer == 0) {
        g_h1T[h * BB + b] = hn;
        out[BB * HH + b * HH + h] = hn;                  // h stack, layer 0
        out[3 * BB * HH + b * HH + h] = cn;              // c stack, layer 0
    } else {
        out[b * HH + h] = hn;                            // output (B,1,H)
        out[2 * BB * HH + b * HH + h] = hn;              // h stack, layer 1
        out[4 * BB * HH + b * HH + h] = cn;              // c stack, layer 1
    }
}

// ---------------------------------------------------------------------------
extern "C" void kernel_launch(void* const* d_in, const int* in_sizes, int n_in,
                              void* d_out, int out_size) {
    const float* input = (const float*)d_in[0];
    const float* h0    = (const float*)d_in[1];
    const float* c0    = (const float*)d_in[2];
    const float* enc   = (const float*)d_in[3];
    const float* attW  = (const float*)d_in[4];
    const float* attb  = (const float*)d_in[5];
    const float* inpW  = (const float*)d_in[6];
    const float* inpb  = (const float*)d_in[7];
    const float* Wih0  = (const float*)d_in[8];
    const float* Whh0  = (const float*)d_in[9];
    const float* bih0  = (const float*)d_in[10];
    const float* bhh0  = (const float*)d_in[11];
    const float* Wih1  = (const float*)d_in[12];
    const float* Whh1  = (const float*)d_in[13];
    const float* bih1  = (const float*)d_in[14];
    const float* bhh1  = (const float*)d_in[15];
    float* out = (float*)d_out;

    const int smem1 = ((WC + 1) * HH + 132 + 8) * (int)sizeof(float);  // ~65.1 KB
    const int smem2 = 2 * HH * BB * (int)sizeof(float);                // 64 KB
    cudaFuncSetAttribute(attn_partial, cudaFuncAttributeMaxDynamicSharedMemorySize, smem1);
    cudaFuncSetAttribute(xin_gemv,   cudaFuncAttributeMaxDynamicSharedMemorySize, smem2);
    cudaFuncSetAttribute(gates_gemv, cudaFuncAttributeMaxDynamicSharedMemorySize, smem2);

    attn_partial<<<dim3(CHUNKS, BB), NT1, smem1>>>(enc, h0, c0, attW, attb);
    combine_stage<<<BB, 128>>>(input, h0);
    xin_gemv<<<16, 256, smem2>>>(inpW, inpb);
    gates_gemv<<<64, 256, smem2>>>(Wih0, Whh0, bih0, bhh0, 0);
    lstm_elem<<<16, 512>>>(c0, out, 0);
    gates_gemv<<<64, 256, smem2>>>(Wih1, Whh1, bih1, bhh1, 1);
    lstm_elem<<<16, 512>>>(c0, out, 1);
}

// round 15
// speedup vs baseline: 1.6484x; 1.6484x over previous
#include <cuda_runtime.h>
#include <math.h>

#define BB 64
#define WW 4096
#define HH 128
#define RPW 32                 // rows per warp (attn)
#define NW 8                   // warps per attn CTA
#define CROWS (RPW * NW)       // 256 rows per CTA
#define CHUNKS (WW / CROWS)    // 16

// ---------------- scratch (__device__ globals, allocation-free) -------------
// NEVER pass these as host-side kernel args (ATS shadow-symbol trap).
__device__ float g_m[BB * CHUNKS];
__device__ float g_s[BB * CHUNKS];
__device__ float g_acc[BB * CHUNKS * HH];
__device__ float g_xT[2 * HH * BB];      // xcat transposed [k][b]
__device__ float g_h0l0T[HH * BB];       // h0 layer0 transposed [h][b]
__device__ float g_h0l1T[HH * BB];       // h0 layer1 transposed
__device__ float g_h1T[HH * BB];         // h1 (LSTM0 out) transposed
__device__ float g_xinT[HH * BB];        // xin transposed [r][b] (bias included)
__device__ float g_gp[2 * 4 * HH * BB];  // gate partials [slice][g][b]

// ---------------------------------------------------------------------------
// Kernel 1: attention, register-resident online softmax. No enc SMEM.
// grid (CHUNKS, BB) x 256 threads. Warp w owns weight rows
// [c*256 + w*32, +32); per row: 1 float4/lane LDG + shfl score + online update.
// ---------------------------------------------------------------------------
__global__ __launch_bounds__(256) void attn_partial(
    const float* __restrict__ enc,   // (B, W, H)
    const float* __restrict__ h0,    // (2, B, H)
    const float* __restrict__ c0,    // (2, B, H)
    const float* __restrict__ attW,  // (1, 2H)
    const float* __restrict__ attb)  // (1,)
{
    __shared__ float sm_m[NW], sm_s[NW];
    __shared__ float4 sm_acc[NW][32];

    const int b = blockIdx.y, c = blockIdx.x;
    const int t = threadIdx.x, lane = t & 31, wrp = t >> 5;

    // ---- tbias = att_state[b].wa_st + att_b (computed per warp) ----
    const float4 wst = reinterpret_cast<const float4*>(attW + HH)[lane];
    const float4 hv  = reinterpret_cast<const float4*>(h0 + (BB + b) * HH)[lane];
    const float4 cv  = reinterpret_cast<const float4*>(c0 + (BB + b) * HH)[lane];
    float tb = hv.x * cv.x * wst.x + hv.y * cv.y * wst.y
             + hv.z * cv.z * wst.z + hv.w * cv.w * wst.w;
    #pragma unroll
    for (int o = 16; o > 0; o >>= 1) tb += __shfl_xor_sync(0xffffffffu, tb, o);
    const float tbias = tb + attb[0];

    const float4 wa = reinterpret_cast<const float4*>(attW)[lane];
    const float4* rowv = reinterpret_cast<const float4*>(enc) + (long)b * WW * 32;

    const int rstart = c * CROWS + wrp * RPW;

    // score of row rstart-1 (logit of weight rstart); weight 0 -> logit 0
    float s_prev;
    if (rstart > 0) {
        float4 v = rowv[(long)(rstart - 1) * 32 + lane];
        float d = v.x * wa.x + v.y * wa.y + v.z * wa.z + v.w * wa.w;
        #pragma unroll
        for (int o = 16; o > 0; o >>= 1) d += __shfl_xor_sync(0xffffffffu, d, o);
        s_prev = d + tbias;
    } else {
        s_prev = 0.f;
    }

    float m = -INFINITY, S = 0.f;
    float4 acc = make_float4(0.f, 0.f, 0.f, 0.f);
    float4 v_cur = rowv[(long)rstart * 32 + lane];

    #pragma unroll 4
    for (int i = 0; i < RPW; ++i) {
        float4 v_next = make_float4(0.f, 0.f, 0.f, 0.f);
        if (i < RPW - 1) v_next = rowv[(long)(rstart + i + 1) * 32 + lane];  // prefetch

        float d = v_cur.x * wa.x + v_cur.y * wa.y + v_cur.z * wa.z + v_cur.w * wa.w;
        #pragma unroll
        for (int o = 16; o > 0; o >>= 1) d += __shfl_xor_sync(0xffffffffu, d, o);
        const float sc = d + tbias;          // score of row rstart+i = logit of weight rstart+i+1

        const float l = s_prev;              // logit of weight rstart+i
        const float mn = fmaxf(m, l);
        const float f = __expf(m - mn);      // m=-inf first iter -> f=0
        const float p = __expf(l - mn);
        S = S * f + p;
        acc.x = acc.x * f + p * v_cur.x;
        acc.y = acc.y * f + p * v_cur.y;
        acc.z = acc.z * f + p * v_cur.z;
        acc.w = acc.w * f + p * v_cur.w;
        m = mn;
        s_prev = sc;
        v_cur = v_next;
    }

    // ---- merge 8 warp partials within CTA ----
    if (lane == 0) { sm_m[wrp] = m; sm_s[wrp] = S; }
    sm_acc[wrp][lane] = acc;
    __syncthreads();
    if (wrp == 0) {
        float M = sm_m[0];
        #pragma unroll
        for (int g = 1; g < NW; ++g) M = fmaxf(M, sm_m[g]);
        float Ssum = 0.f;
        float4 a = make_float4(0.f, 0.f, 0.f, 0.f);
        #pragma unroll
        for (int g = 0; g < NW; ++g) {
            float e = __expf(sm_m[g] - M);
            Ssum += sm_s[g] * e;
            float4 w4 = sm_acc[g][lane];
            a.x += e * w4.x; a.y += e * w4.y; a.z += e * w4.z; a.w += e * w4.w;
        }
        reinterpret_cast<float4*>(g_acc + (b * CHUNKS + c) * HH)[lane] = a;
        if (lane == 0) { g_m[b * CHUNKS + c] = M; g_s[b * CHUNKS + c] = Ssum; }
    }
}

// ---------------------------------------------------------------------------
// K2a: combine chunk partials -> context x; stage transposed activations.
// ---------------------------------------------------------------------------
__global__ __launch_bounds__(128) void combine_stage(
    const float* __restrict__ input, const float* __restrict__ h0)
{
    const int b = blockIdx.x, t = threadIdx.x;   // t < 128
    float M = -INFINITY;
    #pragma unroll
    for (int c = 0; c < CHUNKS; ++c) M = fmaxf(M, g_m[b * CHUNKS + c]);
    float S = 0.f, a = 0.f;
    #pragma unroll
    for (int c = 0; c < CHUNKS; ++c) {
        float e = __expf(g_m[b * CHUNKS + c] - M);
        S += g_s[b * CHUNKS + c] * e;
        a += g_acc[(b * CHUNKS + c) * HH + t] * e;
    }
    g_xT[t * BB + b] = a / S;
    g_xT[(HH + t) * BB + b] = input[b * HH + t];
    g_h0l0T[t * BB + b] = h0[b * HH + t];
    g_h0l1T[t * BB + b] = h0[BB * HH + b * HH + t];
}

// ---------------------------------------------------------------------------
// K2b: xin[r][b] = inpb[r] + sum_k inpW[r][k] * xcat[k][b].
// Thread = (r, b): weights broadcast within warp, x coalesced across b.
// grid 16 x 512 (8 rows per CTA).
// ---------------------------------------------------------------------------
__global__ __launch_bounds__(512) void xin_gemv(
    const float* __restrict__ inpW, const float* __restrict__ inpb)
{
    const int t = threadIdx.x;
    const int r = blockIdx.x * 8 + (t >> 6);
    const int b = t & 63;
    const float* wrow = inpW + r * (2 * HH);
    float a0 = 0.f, a1 = 0.f, a2 = 0.f, a3 = 0.f;
    #pragma unroll 8
    for (int k = 0; k < 2 * HH; k += 4) {
        a0 += wrow[k]     * g_xT[(k)     * BB + b];
        a1 += wrow[k + 1] * g_xT[(k + 1) * BB + b];
        a2 += wrow[k + 2] * g_xT[(k + 2) * BB + b];
        a3 += wrow[k + 3] * g_xT[(k + 3) * BB + b];
    }
    g_xinT[r * BB + b] = a0 + a1 + a2 + a3 + inpb[r];
}

// ---------------------------------------------------------------------------
// K2c: gate partials. grid (64, 2) x 512. blockIdx.y: 0 = Wih*x, 1 = Whh*h.
// Activation source picked from g_* scratch in DEVICE code via layer flag.
// ---------------------------------------------------------------------------
__global__ __launch_bounds__(512) void gates_gemv(
    const float* __restrict__ Wih, const float* __restrict__ Whh, int layer)
{
    const int t = threadIdx.x;
    const int g = blockIdx.x * 8 + (t >> 6);
    const int b = t & 63;
    const int slice = blockIdx.y;
    const float* W = slice ? Whh : Wih;
    const float* X = slice ? (layer ? g_h0l1T : g_h0l0T)
                           : (layer ? g_h1T   : g_xinT);
    const float* wrow = W + g * HH;
    float a0 = 0.f, a1 = 0.f, a2 = 0.f, a3 = 0.f;
    #pragma unroll 8
    for (int k = 0; k < HH; k += 4) {
        a0 += wrow[k]     * X[(k)     * BB + b];
        a1 += wrow[k + 1] * X[(k + 1) * BB + b];
        a2 += wrow[k + 2] * X[(k + 2) * BB + b];
        a3 += wrow[k + 3] * X[(k + 3) * BB + b];
    }
    g_gp[slice * 4 * HH * BB + g * BB + b] = a0 + a1 + a2 + a3;
}

// ---------------------------------------------------------------------------
// K2d: LSTM elementwise (partials + biases).
// ---------------------------------------------------------------------------
__device__ __forceinline__ float sigmoidf_(float v) { return 1.0f / (1.0f + __expf(-v)); }

__global__ __launch_bounds__(512) void lstm_elem(
    const float* __restrict__ bih, const float* __restrict__ bhh,
    const float* __restrict__ c0,      // base device pointer
    float* __restrict__ out, int layer)
{
    const float* c0ptr = c0 + layer * BB * HH;
    const int idx = blockIdx.x * 512 + threadIdx.x;  // 0..8191
    const int b = idx & 63, h = idx >> 6;
    float G[4];
    #pragma unroll
    for (int j = 0; j < 4; ++j) {
        const int g = j * HH + h;
        G[j] = bih[g] + bhh[g] + g_gp[g * BB + b] + g_gp[4 * HH * BB + g * BB + b];
    }
    float ig = sigmoidf_(G[0]);
    float fg = sigmoidf_(G[1]);
    float gg = tanhf(G[2]);
    float og = sigmoidf_(G[3]);
    float cn = fg * c0ptr[b * HH + h] + ig * gg;
    float hn = og * tanhf(cn);
    if (layer == 0) {
        g_h1T[h * BB + b] = hn;
        out[BB * HH + b * HH + h] = hn;                  // h stack, layer 0
        out[3 * BB * HH + b * HH + h] = cn;              // c stack, layer 0
    } else {
        out[b * HH + h] = hn;                            // output (B,1,H)
        out[2 * BB * HH + b * HH + h] = hn;              // h stack, layer 1
        out[4 * BB * HH + b * HH + h] = cn;              // c stack, layer 1
    }
}

// ---------------------------------------------------------------------------
extern "C" void kernel_launch(void* const* d_in, const int* in_sizes, int n_in,
                              void* d_out, int out_size) {
    const float* input = (const float*)d_in[0];
    const float* h0    = (const float*)d_in[1];
    const float* c0    = (const float*)d_in[2];
    const float* enc   = (const float*)d_in[3];
    const float* attW  = (const float*)d_in[4];
    const float* attb  = (const float*)d_in[5];
    const float* inpW  = (const float*)d_in[6];
    const float* inpb  = (const float*)d_in[7];
    const float* Wih0  = (const float*)d_in[8];
    const float* Whh0  = (const float*)d_in[9];
    const float* bih0  = (const float*)d_in[10];
    const float* bhh0  = (const float*)d_in[11];
    const float* Wih1  = (const float*)d_in[12];
    const float* Whh1  = (const float*)d_in[13];
    const float* bih1  = (const float*)d_in[14];
    const float* bhh1  = (const float*)d_in[15];
    float* out = (float*)d_out;

    attn_partial<<<dim3(CHUNKS, BB), 256>>>(enc, h0, c0, attW, attb);
    combine_stage<<<BB, 128>>>(input, h0);
    xin_gemv<<<16, 512>>>(inpW, inpb);
    gates_gemv<<<dim3(64, 2), 512>>>(Wih0, Whh0, 0);
    lstm_elem<<<16, 512>>>(bih0, bhh0, c0, out, 0);
    gates_gemv<<<dim3(64, 2), 512>>>(Wih1, Whh1, 1);
    lstm_elem<<<16, 512>>>(bih1, bhh1, c0, out, 1);
}